// round 1
// baseline (speedup 1.0000x reference)
#include <cuda_runtime.h>
#include <cuda_bf16.h>
#include <stdint.h>

#define NB 16
#define NA 25200
#define NCLS 80
#define PS 85
#define KC 1024
#define CAP 2048
#define MAXDET 300
#define BINS 1024
#define CONF_T 0.4f
#define IOU_T 0.25f

#define DETS_OFF 0
#define VALID_OFF (NB*MAXDET*6)            // 28800
#define FEATS_OFF (VALID_OFF + NB*MAXDET)  // 33600
#define FEATS_LEN (MAXDET*82)              // 24600

// ---------------- device scratch (no allocs allowed) ----------------
__device__ float               g_scores[NB*NA];
__device__ int                 g_cls[NB*NA];
__device__ unsigned int        g_hist[NB*BINS];     // zero-initialized at load; re-zeroed in k_thresh
__device__ int                 g_tb[NB];
__device__ int                 g_cnt[NB];           // zero-initialized; re-zeroed in k_thresh
__device__ unsigned long long  g_keys[NB*CAP];
__device__ float4              g_boxes[NB*KC];
__device__ float               g_area[NB*KC];
__device__ float               g_tscore[NB*KC];
__device__ int                 g_tcls[NB*KC];
__device__ unsigned int        g_validw[NB*32];
__device__ unsigned int        g_mask[NB*KC*32];    // 2 MB suppression bit matrix
__device__ unsigned int        g_keepw[NB*32];

__device__ __forceinline__ int score_bin(float s) {
    float bf = __fmul_rn(__fsub_rn(s, CONF_T), (float)BINS / 0.6f);
    int b = (int)bf;
    return b > (BINS-1) ? (BINS-1) : (b < 0 ? 0 : b);
}

// ---------------- 1) score + histogram ----------------
// block: 256 threads, 128 anchors staged to shared via float4
__global__ void __launch_bounds__(256) k_score(const float* __restrict__ pred) {
    __shared__ float sb[128*PS];
    const int b   = blockIdx.y;
    const int a0  = blockIdx.x * 128;
    const int tid = threadIdx.x;
    const int na  = (NA - a0) < 128 ? (NA - a0) : 128;

    const float* base = pred + ((size_t)b * NA + a0) * PS;
    const int total4 = (na * PS) >> 2;           // na*85 always divisible by 4 here
    const float4* g4 = (const float4*)base;
    float4* s4 = (float4*)sb;
    for (int i = tid; i < total4; i += 256) s4[i] = g4[i];
    __syncthreads();

    if (tid < na) {
        const float* p = sb + tid * PS;
        const float obj = p[4];
        float best = -1e30f; int arg = 0;
        #pragma unroll 8
        for (int c = 0; c < NCLS; c++) {
            float v = __fmul_rn(p[5 + c], obj);   // match ref: per-class product, then max
            if (v > best) { best = v; arg = c; }  // strict > keeps lowest index (argmax tie rule)
        }
        const bool cand = (obj > CONF_T) && (best > CONF_T);
        const int n = a0 + tid;
        g_scores[b*NA + n] = cand ? best : -1.0f;
        g_cls[b*NA + n]    = arg;
        if (cand) atomicAdd(&g_hist[b*BINS + score_bin(best)], 1u);
    }
}

// ---------------- 2) per-batch threshold bin; reset hist/cnt ----------------
__global__ void __launch_bounds__(32) k_thresh() {
    const int b = blockIdx.x, lane = threadIdx.x;
    unsigned cum = 0; int tb = 0;
    for (int base = BINS - 32; base >= 0; base -= 32) {
        unsigned v = g_hist[b*BINS + base + lane];
        unsigned suf = v;                              // inclusive suffix sum within warp
        #pragma unroll
        for (int off = 1; off < 32; off <<= 1) {
            unsigned y = __shfl_down_sync(0xffffffffu, suf, off);
            if (lane < 32 - off) suf += y;
        }
        unsigned S = cum + suf;                        // count with bin >= base+lane
        unsigned bal = __ballot_sync(0xffffffffu, S >= (unsigned)KC);
        if (bal) { tb = base + (31 - __clz(bal)); break; }
        cum += __shfl_sync(0xffffffffu, suf, 0);
        if (base == 0) tb = 0;                         // fewer than KC candidates total
    }
    if (lane == 0) { g_tb[b] = tb; g_cnt[b] = 0; }
    for (int i = lane; i < BINS; i += 32) g_hist[b*BINS + i] = 0;  // ready for next replay
}

// ---------------- 3) gather candidates above threshold bin ----------------
__global__ void __launch_bounds__(256) k_gather() {
    const int i = blockIdx.x * 256 + threadIdx.x;
    if (i >= NB*NA) return;
    const float s = g_scores[i];
    if (s > 0.0f) {
        const int b = i / NA;
        if (score_bin(s) >= g_tb[b]) {
            int pos = atomicAdd(&g_cnt[b], 1);
            if (pos < CAP) {
                unsigned ob = ~__float_as_uint(s);     // all scores > 0 -> bits order-preserving
                g_keys[b*CAP + pos] =
                    ((unsigned long long)ob << 32) | (unsigned)(i - b * NA);
            }
        }
    }
}

// ---------------- 4) bitonic sort 2048 keys; emit sorted top-1024 boxes ----------------
__global__ void __launch_bounds__(1024) k_sort(const float* __restrict__ pred) {
    __shared__ unsigned long long sk[CAP];
    const int b = blockIdx.x, tid = threadIdx.x;
    int cnt = g_cnt[b]; if (cnt > CAP) cnt = CAP;

    for (int s = tid; s < CAP; s += 1024)
        sk[s] = (s < cnt) ? g_keys[b*CAP + s] : 0xFFFFFFFFFFFFFFFFull;

    for (int size = 2; size < CAP; size <<= 1) {
        const unsigned ddd = (tid & (size >> 1)) != 0;
        for (int stride = size >> 1; stride > 0; stride >>= 1) {
            __syncthreads();
            const int pos = 2*tid - (tid & (stride - 1));
            unsigned long long A = sk[pos], B = sk[pos + stride];
            if (((A > B) ? 1u : 0u) == ddd) { sk[pos] = B; sk[pos + stride] = A; }
        }
    }
    for (int stride = CAP >> 1; stride > 0; stride >>= 1) {   // final ascending merge
        __syncthreads();
        const int pos = 2*tid - (tid & (stride - 1));
        unsigned long long A = sk[pos], B = sk[pos + stride];
        if (A > B) { sk[pos] = B; sk[pos + stride] = A; }
    }
    __syncthreads();

    const int vcnt = cnt < KC ? cnt : KC;
    const bool valid0 = tid < vcnt;
    float4 box = make_float4(0.f, 0.f, 0.f, 0.f);
    float area = 0.f, conf = 0.f; int cls = 0;
    if (valid0) {
        const unsigned long long key = sk[tid];
        const unsigned anchor = (unsigned)(key & 0xffffffffull);
        conf = __uint_as_float(~(unsigned)(key >> 32));
        const size_t pidx = ((size_t)b * NA + anchor) * PS;
        const float cx = pred[pidx + 0], cy = pred[pidx + 1];
        const float w  = pred[pidx + 2], h  = pred[pidx + 3];
        const float hw = __fmul_rn(w, 0.5f), hh = __fmul_rn(h, 0.5f);
        box.x = __fsub_rn(cx, hw); box.y = __fsub_rn(cy, hh);
        box.z = __fadd_rn(cx, hw); box.w = __fadd_rn(cy, hh);
        area  = __fmul_rn(__fsub_rn(box.z, box.x), __fsub_rn(box.w, box.y));
        cls   = g_cls[b*NA + anchor];
    }
    g_boxes[b*KC + tid]  = box;
    g_area[b*KC + tid]   = area;
    g_tscore[b*KC + tid] = conf;
    g_tcls[b*KC + tid]   = cls;
    const unsigned bal = __ballot_sync(0xffffffffu, valid0);
    if ((tid & 31) == 0) g_validw[b*32 + (tid >> 5)] = bal;
}

// exact (vs JAX fp32) iou > 0.25: fast multiply-compare, IEEE div only near threshold
__device__ __forceinline__ bool iou_gt(float4 A, float aA, float4 B, float aB) {
    const float ltx = fmaxf(A.x, B.x), lty = fmaxf(A.y, B.y);
    const float rbx = fminf(A.z, B.z), rby = fminf(A.w, B.w);
    const float wx = fmaxf(__fsub_rn(rbx, ltx), 0.0f);
    const float wy = fmaxf(__fsub_rn(rby, lty), 0.0f);
    const float inter = __fmul_rn(wx, wy);
    const float denom = __fadd_rn(__fsub_rn(__fadd_rn(aA, aB), inter), 1e-9f);
    const float hi = __fmul_rn(IOU_T, denom);         // *0.25 is exact
    if (inter > __fmul_rn(hi, 1.00001f)) return true;
    if (inter < __fmul_rn(hi, 0.99999f)) return false;
    return __fdiv_rn(inter, denom) > IOU_T;
}

// ---------------- 5) suppression bit matrix ----------------
// grid (8, NB), block 256 (8 warps); each warp: 16 rows, 32 ballots/row
__global__ void __launch_bounds__(256) k_mask() {
    __shared__ float4 sbx[KC];
    __shared__ float  sar[KC];
    const int b = blockIdx.y, tid = threadIdx.x;
    for (int i = tid; i < KC; i += 256) { sbx[i] = g_boxes[b*KC + i]; sar[i] = g_area[b*KC + i]; }
    __syncthreads();
    const int warp = tid >> 5, lane = tid & 31;
    for (int r = 0; r < 16; r++) {
        const int i = blockIdx.x * 128 + warp * 16 + r;
        const float4 A = sbx[i]; const float aA = sar[i];
        unsigned rowword = 0;
        #pragma unroll 4
        for (int w = 0; w < 32; w++) {
            const int j = w * 32 + lane;
            const bool c = (j > i) && iou_gt(A, aA, sbx[j], sar[j]);
            const unsigned bal = __ballot_sync(0xffffffffu, c);
            if (w == lane) rowword = bal;
        }
        g_mask[((size_t)(b*KC + i)) * 32 + lane] = rowword;
    }
}

// ---------------- 6) greedy-NMS serial scan, one warp per batch ----------------
__global__ void __launch_bounds__(32) k_scan() {
    const int b = blockIdx.x, lane = threadIdx.x;
    unsigned removed = 0;   // lane owns columns [lane*32, lane*32+32)
    for (int w = 0; w < 32; w++) {
        const unsigned validword = g_validw[b*32 + w];
        const unsigned curRem = __shfl_sync(0xffffffffu, removed, w);
        bool alive = ((validword >> lane) & 1u) && !((curRem >> lane) & 1u);
        unsigned r[32];
        #pragma unroll
        for (int k = 0; k < 32; k++)
            r[k] = g_mask[((size_t)(b*KC + w*32 + k)) * 32 + lane];
        // transpose diagonal 32x32 block: colmask bit k = (row w*32+k suppresses my column)
        unsigned colmask = 0;
        #pragma unroll
        for (int k = 0; k < 32; k++) {
            const unsigned dw = __shfl_sync(0xffffffffu, r[k], w);
            colmask |= ((dw >> lane) & 1u) << k;
        }
        // resolve intra-chunk greedy dependency
        for (int k = 0; k < 32; k++) {
            const unsigned am = __ballot_sync(0xffffffffu, alive);
            if ((am >> k) & 1u) alive = alive && !((colmask >> k) & 1u);
        }
        const unsigned keep = __ballot_sync(0xffffffffu, alive);
        if (lane == 0) g_keepw[b*32 + w] = keep;
        #pragma unroll
        for (int k = 0; k < 32; k++)
            if ((keep >> k) & 1u) removed |= r[k];
    }
}

// ---------------- 7) compact kept rows -> dets/valid/feats ----------------
__global__ void __launch_bounds__(1024) k_out(float* __restrict__ out,
                                              const int* __restrict__ imgp,
                                              int hasValid, int hasFeats) {
    __shared__ int wpre[32];
    const int b = blockIdx.x, tid = threadIdx.x;
    const int wid = tid >> 5, lane = tid & 31;
    const unsigned kw = g_keepw[b*32 + wid];
    if (tid < 32) {
        int v = __popc(g_keepw[b*32 + tid]);
        int x = v;
        #pragma unroll
        for (int off = 1; off < 32; off <<= 1) {
            int y = __shfl_up_sync(0xffffffffu, x, off);
            if (tid >= off) x += y;
        }
        wpre[tid] = x - v;
    }
    __syncthreads();
    const bool keep = (kw >> lane) & 1u;
    const int rank = wpre[wid] + __popc(kw & ((1u << lane) - 1u));
    if (keep && rank < MAXDET) {
        const int idx = b*KC + tid;
        const float4 f = g_boxes[idx];
        const float sc = g_tscore[idx];
        const int   c  = g_tcls[idx];
        float* d = out + ((size_t)b * MAXDET + rank) * 6;
        d[0] = f.x; d[1] = f.y; d[2] = f.z; d[3] = f.w; d[4] = sc; d[5] = (float)c;
        if (hasValid) out[VALID_OFF + b*MAXDET + rank] = 1.0f;
        if (hasFeats && b == 0) {
            float scale = 1.0f / 640.0f;
            if (imgp) {
                int iv = imgp[0];
                if (iv > 0 && iv < 1000000) scale = 1.0f / (float)iv;
                else                        scale = 1.0f / __int_as_float(iv);
            }
            const size_t fo = (size_t)FEATS_OFF + (size_t)rank * 82;
            out[fo + 0] = __fmul_rn(__fmul_rn(__fadd_rn(f.x, f.z), 0.5f), scale);
            out[fo + 1] = __fmul_rn(__fmul_rn(__fadd_rn(f.y, f.w), 0.5f), scale);
            out[fo + 2 + c] = 1.0f;
        }
    }
}

extern "C" void kernel_launch(void* const* d_in, const int* in_sizes, int n_in,
                              void* d_out, int out_size) {
    const float* pred = (const float*)d_in[0];
    const int*   img  = (n_in > 1) ? (const int*)d_in[1] : nullptr;
    if (n_in > 1 && in_sizes[0] == 1) {     // defensive: metadata order swapped
        img  = (const int*)d_in[0];
        pred = (const float*)d_in[1];
    }
    float* out = (float*)d_out;

    cudaMemsetAsync(d_out, 0, (size_t)out_size * sizeof(float), 0);

    k_score <<<dim3((NA + 127) / 128, NB), 256>>>(pred);
    k_thresh<<<NB, 32>>>();
    k_gather<<<(NB*NA + 255) / 256, 256>>>();
    k_sort  <<<NB, 1024>>>(pred);
    k_mask  <<<dim3(8, NB), 256>>>();
    k_scan  <<<NB, 32>>>();

    const int hasValid = out_size >= VALID_OFF + NB*MAXDET;
    const int hasFeats = out_size >= FEATS_OFF + FEATS_LEN;
    k_out   <<<NB, 1024>>>(out, img, hasValid, hasFeats);
}

// round 3
// speedup vs baseline: 1.1198x; 1.1198x over previous
#include <cuda_runtime.h>
#include <cuda_bf16.h>
#include <stdint.h>

#define NB 16
#define NA 25200
#define NCLS 80
#define PS 85
#define KC 1024
#define CAP 2048
#define MAXDET 300
#define BINS 1024
#define CONF_T 0.4f
#define IOU_T 0.25f

#define DETS_OFF 0
#define VALID_OFF (NB*MAXDET*6)            // 28800
#define FEATS_OFF (VALID_OFF + NB*MAXDET)  // 33600
#define FEATS_LEN (MAXDET*82)              // 24600

typedef unsigned long long ull;
#define FULLM 0xffffffffu

// ---------------- device scratch (no allocs allowed) ----------------
__device__ float               g_scores[NB*NA];
__device__ int                 g_cls[NB*NA];
__device__ unsigned int        g_hist[NB*BINS];   // zero at load; re-zeroed each call in k_prep
__device__ float4              g_boxes[NB*KC];
__device__ float               g_area[NB*KC];
__device__ float               g_tscore[NB*KC];
__device__ int                 g_tcls[NB*KC];
__device__ unsigned int        g_validw[NB*32];
__device__ unsigned int        g_mask[NB*KC*32];  // lower-triangle words never written (stay 0)

__device__ __forceinline__ int score_bin(float s) {
    float bf = __fmul_rn(__fsub_rn(s, CONF_T), (float)BINS / 0.6f);
    int b = (int)bf;
    return b > (BINS-1) ? (BINS-1) : (b < 0 ? 0 : b);
}

// ---------------- 1) score + histogram ----------------
__global__ void __launch_bounds__(256) k_score(const float* __restrict__ pred) {
    __shared__ float sb[128*PS];
    const int b   = blockIdx.y;
    const int a0  = blockIdx.x * 128;
    const int tid = threadIdx.x;
    const int na  = (NA - a0) < 128 ? (NA - a0) : 128;

    const float* base = pred + ((size_t)b * NA + a0) * PS;
    const int total4 = (na * PS) >> 2;
    const float4* g4 = (const float4*)base;
    float4* s4 = (float4*)sb;
    for (int i = tid; i < total4; i += 256) s4[i] = g4[i];
    __syncthreads();

    if (tid < na) {
        const float* p = sb + tid * PS;
        const float obj = p[4];
        float best = -1e30f; int arg = 0;
        #pragma unroll 8
        for (int c = 0; c < NCLS; c++) {
            float v = __fmul_rn(p[5 + c], obj);
            if (v > best) { best = v; arg = c; }   // strict > = lowest-index argmax tie rule
        }
        const bool cand = (obj > CONF_T) && (best > CONF_T);
        const int n = a0 + tid;
        g_scores[b*NA + n] = cand ? best : -1.0f;
        g_cls[b*NA + n]    = arg;
        if (cand) atomicAdd(&g_hist[b*BINS + score_bin(best)], 1u);
    }
}

// hybrid bitonic compare-exchange: shuffle pass for stride<=16
__device__ __forceinline__ ull casx(ull x, int idx, int stride, int size) {
    ull p = __shfl_xor_sync(FULLM, x, stride);
    bool lower = ((idx & stride) == 0);
    bool up    = ((idx & size)   == 0);
    return (lower == up) ? (x < p ? x : p) : (x > p ? x : p);
}

// ---------------- 2) fused: threshold + gather + sort + box emit (block = batch) ----------
__global__ void __launch_bounds__(1024) k_prep(const float* __restrict__ pred) {
    __shared__ ull sk[CAP];
    __shared__ int s_tb, s_cnt;
    const int b = blockIdx.x, tid = threadIdx.x;

    // --- threshold bin from histogram (warp 0), then re-zero hist for next replay ---
    if (tid < 32) {
        const int lane = tid;
        unsigned cum = 0; int tb = 0;
        for (int base = BINS - 32; base >= 0; base -= 32) {
            unsigned v = g_hist[b*BINS + base + lane];
            unsigned suf = v;
            #pragma unroll
            for (int off = 1; off < 32; off <<= 1) {
                unsigned y = __shfl_down_sync(FULLM, suf, off);
                if (lane < 32 - off) suf += y;
            }
            unsigned S = cum + suf;
            unsigned bal = __ballot_sync(FULLM, S >= (unsigned)KC);
            if (bal) { tb = base + (31 - __clz(bal)); break; }
            cum += __shfl_sync(FULLM, suf, 0);
            if (base == 0) tb = 0;
        }
        if (lane == 0) { s_tb = tb; s_cnt = 0; }
        for (int i = lane; i < BINS; i += 32) g_hist[b*BINS + i] = 0;
    }
    __syncthreads();
    const int tb = s_tb;

    // --- gather candidates straight into shared ---
    for (int n = tid; n < NA; n += 1024) {
        const float s = g_scores[b*NA + n];
        if (s > 0.0f && score_bin(s) >= tb) {
            int pos = atomicAdd(&s_cnt, 1);
            if (pos < CAP) {
                unsigned ob = ~__float_as_uint(s);
                sk[pos] = ((ull)ob << 32) | (unsigned)n;
            }
        }
    }
    __syncthreads();
    int cnt = s_cnt; if (cnt > CAP) cnt = CAP;
    for (int i = cnt + tid; i < CAP; i += 1024) sk[i] = ~0ull;
    __syncthreads();

    // --- bitonic sort of 2048 keys; strides<=32 in registers ---
    const int wp = tid >> 5, l = tid & 31;
    const int base = wp * 64;
    const int ia = base + l, ib = base + 32 + l;
    ull a = sk[ia], bb = sk[ib];

    #pragma unroll
    for (int size = 2; size <= 32; size <<= 1)
        #pragma unroll
        for (int stride = size >> 1; stride > 0; stride >>= 1) {
            a  = casx(a,  ia, stride, size);
            bb = casx(bb, ib, stride, size);
        }
    {   // size = 64: stride 32 is the a<->bb register pair
        bool up = ((ia & 64) == 0);
        if ((a > bb) == up) { ull t = a; a = bb; bb = t; }
        #pragma unroll
        for (int stride = 16; stride > 0; stride >>= 1) {
            a  = casx(a,  ia, stride, 64);
            bb = casx(bb, ib, stride, 64);
        }
    }
    sk[ia] = a; sk[ib] = bb;

    #pragma unroll
    for (int size = 128; size <= CAP; size <<= 1) {
        for (int stride = size >> 1; stride >= 64; stride >>= 1) {
            __syncthreads();
            const int pos = 2*tid - (tid & (stride - 1));
            ull A = sk[pos], B = sk[pos + stride];
            bool up = ((pos & size) == 0);
            if ((A > B) == up) { sk[pos] = B; sk[pos + stride] = A; }
        }
        __syncthreads();
        a = sk[ia]; bb = sk[ib];
        { bool up = ((ia & size) == 0);
          if ((a > bb) == up) { ull t = a; a = bb; bb = t; } }
        #pragma unroll
        for (int stride = 16; stride > 0; stride >>= 1) {
            a  = casx(a,  ia, stride, size);
            bb = casx(bb, ib, stride, size);
        }
        sk[ia] = a; sk[ib] = bb;
    }
    __syncthreads();

    // --- emit top-1024 boxes ---
    const int vcnt = cnt < KC ? cnt : KC;
    const bool valid0 = tid < vcnt;
    float4 box = make_float4(0.f, 0.f, 0.f, 0.f);
    float area = 0.f, conf = 0.f; int cls = 0;
    if (valid0) {
        const ull key = sk[tid];
        const unsigned anchor = (unsigned)(key & 0xffffffffull);
        conf = __uint_as_float(~(unsigned)(key >> 32));
        const size_t pidx = ((size_t)b * NA + anchor) * PS;
        const float cx = pred[pidx + 0], cy = pred[pidx + 1];
        const float w  = pred[pidx + 2], h  = pred[pidx + 3];
        const float hw = __fmul_rn(w, 0.5f), hh = __fmul_rn(h, 0.5f);
        box.x = __fsub_rn(cx, hw); box.y = __fsub_rn(cy, hh);
        box.z = __fadd_rn(cx, hw); box.w = __fadd_rn(cy, hh);
        area  = __fmul_rn(__fsub_rn(box.z, box.x), __fsub_rn(box.w, box.y));
        cls   = g_cls[b*NA + anchor];
    }
    g_boxes[b*KC + tid]  = box;
    g_area[b*KC + tid]   = area;
    g_tscore[b*KC + tid] = conf;
    g_tcls[b*KC + tid]   = cls;
    const unsigned bal = __ballot_sync(FULLM, valid0);
    if ((tid & 31) == 0) g_validw[b*32 + (tid >> 5)] = bal;
}

// exact (vs JAX fp32) iou > 0.25
__device__ __forceinline__ bool iou_gt(float4 A, float aA, float4 B, float aB) {
    const float ltx = fmaxf(A.x, B.x), lty = fmaxf(A.y, B.y);
    const float rbx = fminf(A.z, B.z), rby = fminf(A.w, B.w);
    const float wx = fmaxf(__fsub_rn(rbx, ltx), 0.0f);
    const float wy = fmaxf(__fsub_rn(rby, lty), 0.0f);
    const float inter = __fmul_rn(wx, wy);
    const float denom = __fadd_rn(__fsub_rn(__fadd_rn(aA, aB), inter), 1e-9f);
    const float hi = __fmul_rn(IOU_T, denom);
    if (inter > __fmul_rn(hi, 1.00001f)) return true;
    if (inter < __fmul_rn(hi, 0.99999f)) return false;
    return __fdiv_rn(inter, denom) > IOU_T;
}

// ---------------- 3) suppression bit matrix; rows interleaved across blocks ----------------
__global__ void __launch_bounds__(256) k_mask() {
    __shared__ float4 sbx[KC];
    __shared__ float  sar[KC];
    const int b = blockIdx.y, tid = threadIdx.x;
    for (int i = tid; i < KC; i += 256) { sbx[i] = g_boxes[b*KC + i]; sar[i] = g_area[b*KC + i]; }
    __syncthreads();
    const int warp = tid >> 5, lane = tid & 31;
    for (int r = 0; r < 16; r++) {
        const int i = ((warp * 16 + r) << 3) + blockIdx.x;   // every-8th row per block
        const int w0 = i >> 5;
        const float4 A = sbx[i]; const float aA = sar[i];
        unsigned rowword = 0;
        for (int w = w0; w < 32; w++) {
            const int j = w * 32 + lane;
            const bool c = (j > i) && iou_gt(A, aA, sbx[j], sar[j]);
            const unsigned bal = __ballot_sync(FULLM, c);
            if (w == lane) rowword = bal;
        }
        if (lane >= w0) g_mask[((size_t)(b*KC + i)) * 32 + lane] = rowword;
    }
}

// ---------------- 4) fused greedy scan (shared-staged mask) + output ----------------
__global__ void __launch_bounds__(1024) k_scan_out(float* __restrict__ out,
                                                   const int* __restrict__ imgp,
                                                   int hasValid, int hasFeats) {
    extern __shared__ unsigned smask[];           // 1024 x 32 words = 128 KB
    __shared__ unsigned skeep[32], sval[32];
    __shared__ int wpre[32];
    const int b = blockIdx.x, tid = threadIdx.x;

    const uint4* gm4 = (const uint4*)&g_mask[(size_t)b * KC * 32];
    uint4* sm4 = (uint4*)smask;
    #pragma unroll
    for (int k = 0; k < (KC*32/4)/1024; k++) sm4[k*1024 + tid] = gm4[k*1024 + tid];
    if (tid < 32) sval[tid] = g_validw[b*32 + tid];
    __syncthreads();

    if (tid < 32) {
        const int lane = tid;
        unsigned removed = 0;                     // lane owns columns [lane*32, lane*32+32)
        for (int w = 0; w < 32; w++) {
            const unsigned curRem = __shfl_sync(FULLM, removed, w);
            const unsigned d = smask[(w*32 + lane)*32 + w];   // diag word of row w*32+lane
            unsigned A = sval[w] & ~curRem;       // uniform across lanes
            unsigned keep = 0;
            while (A) {
                const int k = __ffs(A) - 1;
                keep |= (1u << k);
                const unsigned dk = __shfl_sync(FULLM, d, k);
                A &= ~(dk | (1u << k));
            }
            if (lane == 0) skeep[w] = keep;
            unsigned m = keep;
            while (m) {
                const int k = __ffs(m) - 1; m &= m - 1;
                removed |= smask[(w*32 + k)*32 + lane];
            }
        }
    }
    __syncthreads();

    // --- compaction + output ---
    const int wid = tid >> 5, lane = tid & 31;
    const unsigned kw = skeep[wid];
    if (tid < 32) {
        int v = __popc(skeep[tid]);
        int x = v;
        #pragma unroll
        for (int off = 1; off < 32; off <<= 1) {
            int y = __shfl_up_sync(FULLM, x, off);
            if (tid >= off) x += y;
        }
        wpre[tid] = x - v;
    }
    __syncthreads();
    const bool keep = (kw >> lane) & 1u;
    const int rank = wpre[wid] + __popc(kw & ((1u << lane) - 1u));
    if (keep && rank < MAXDET) {
        const int idx = b*KC + tid;
        const float4 f = g_boxes[idx];
        const float sc = g_tscore[idx];
        const int   c  = g_tcls[idx];
        float* d = out + ((size_t)b * MAXDET + rank) * 6;
        d[0] = f.x; d[1] = f.y; d[2] = f.z; d[3] = f.w; d[4] = sc; d[5] = (float)c;
        if (hasValid) out[VALID_OFF + b*MAXDET + rank] = 1.0f;
        if (hasFeats && b == 0) {
            float scale = 1.0f / 640.0f;
            if (imgp) {
                int iv = imgp[0];
                if (iv > 0 && iv < 1000000) scale = 1.0f / (float)iv;
                else                        scale = 1.0f / __int_as_float(iv);
            }
            const size_t fo = (size_t)FEATS_OFF + (size_t)rank * 82;
            out[fo + 0] = __fmul_rn(__fmul_rn(__fadd_rn(f.x, f.z), 0.5f), scale);
            out[fo + 1] = __fmul_rn(__fmul_rn(__fadd_rn(f.y, f.w), 0.5f), scale);
            out[fo + 2 + c] = 1.0f;
        }
    }
}

extern "C" void kernel_launch(void* const* d_in, const int* in_sizes, int n_in,
                              void* d_out, int out_size) {
    const float* pred = (const float*)d_in[0];
    const int*   img  = (n_in > 1) ? (const int*)d_in[1] : nullptr;
    if (n_in > 1 && in_sizes[0] == 1) {
        img  = (const int*)d_in[0];
        pred = (const float*)d_in[1];
    }
    float* out = (float*)d_out;

    (void)cudaFuncSetAttribute(k_scan_out, cudaFuncAttributeMaxDynamicSharedMemorySize, KC*32*4);

    cudaMemsetAsync(d_out, 0, (size_t)out_size * sizeof(float), 0);

    k_score <<<dim3((NA + 127) / 128, NB), 256>>>(pred);
    k_prep  <<<NB, 1024>>>(pred);
    k_mask  <<<dim3(8, NB), 256>>>();

    const int hasValid = out_size >= VALID_OFF + NB*MAXDET;
    const int hasFeats = out_size >= FEATS_OFF + FEATS_LEN;
    k_scan_out<<<NB, 1024, KC*32*4>>>(out, img, hasValid, hasFeats);
}

// round 8
// speedup vs baseline: 1.5779x; 1.4092x over previous
#include <cuda_runtime.h>
#include <cuda_bf16.h>
#include <stdint.h>

#define NB 16
#define NA 25200
#define NCLS 80
#define PS 85
#define KC 1024
#define CAP 2048
#define MAXDET 300
#define BINS 1024
#define CONF_T 0.4f
#define IOU_T 0.25f

#define DETS_OFF 0
#define VALID_OFF (NB*MAXDET*6)            // 28800
#define FEATS_OFF (VALID_OFF + NB*MAXDET)  // 33600
#define FEATS_LEN (MAXDET*82)              // 24600

#define SCAN_PITCH 33                      // odd => conflict-free LDS row stride
#define SCAN_SMEM (KC*SCAN_PITCH*4)        // 135168 B dynamic shared

typedef unsigned long long ull;
#define FULLM 0xffffffffu

// ---------------- device scratch (no allocs allowed) ----------------
__device__ float               g_scores[NB*NA];
__device__ int                 g_cls[NB*NA];
__device__ unsigned int        g_hist[NB*BINS];   // zero at load; re-zeroed each call in k_prep
__device__ float4              g_boxes[NB*KC];
__device__ float               g_area[NB*KC];
__device__ float               g_tscore[NB*KC];
__device__ int                 g_tcls[NB*KC];
__device__ unsigned int        g_validw[NB*32];
__device__ unsigned int        g_mask[NB*KC*32];  // lower-triangle+diag words only are live

__device__ __forceinline__ int score_bin(float s) {
    float bf = __fmul_rn(__fsub_rn(s, CONF_T), (float)BINS / 0.6f);
    int b = (int)bf;
    return b > (BINS-1) ? (BINS-1) : (b < 0 ? 0 : b);
}

// ---------------- 1) score + histogram ----------------
__global__ void __launch_bounds__(256) k_score(const float* __restrict__ pred) {
    __shared__ float sb[128*PS];
    const int b   = blockIdx.y;
    const int a0  = blockIdx.x * 128;
    const int tid = threadIdx.x;
    const int na  = (NA - a0) < 128 ? (NA - a0) : 128;

    const float* base = pred + ((size_t)b * NA + a0) * PS;
    const int total4 = (na * PS) >> 2;
    const float4* g4 = (const float4*)base;
    float4* s4 = (float4*)sb;
    for (int i = tid; i < total4; i += 256) s4[i] = g4[i];
    __syncthreads();

    if (tid < na) {
        const float* p = sb + tid * PS;
        const float obj = p[4];
        float best = -1e30f; int arg = 0;
        #pragma unroll 8
        for (int c = 0; c < NCLS; c++) {
            float v = __fmul_rn(p[5 + c], obj);
            if (v > best) { best = v; arg = c; }   // strict > = lowest-index argmax tie rule
        }
        const bool cand = (obj > CONF_T) && (best > CONF_T);
        const int n = a0 + tid;
        g_scores[b*NA + n] = cand ? best : -1.0f;
        g_cls[b*NA + n]    = arg;
        if (cand) atomicAdd(&g_hist[b*BINS + score_bin(best)], 1u);
    }
}

// hybrid bitonic compare-exchange: shuffle pass for stride<=16
__device__ __forceinline__ ull casx(ull x, int idx, int stride, int size) {
    ull p = __shfl_xor_sync(FULLM, x, stride);
    bool lower = ((idx & stride) == 0);
    bool up    = ((idx & size)   == 0);
    return (lower == up) ? (x < p ? x : p) : (x > p ? x : p);
}

// ---------------- 2) fused: threshold + gather + sort + box emit (block = batch) ----------
__global__ void __launch_bounds__(1024) k_prep(const float* __restrict__ pred) {
    __shared__ ull sk[CAP];
    __shared__ int s_tb, s_cnt;
    const int b = blockIdx.x, tid = threadIdx.x;

    if (tid < 32) {
        const int lane = tid;
        unsigned cum = 0; int tb = 0;
        for (int base = BINS - 32; base >= 0; base -= 32) {
            unsigned v = g_hist[b*BINS + base + lane];
            unsigned suf = v;
            #pragma unroll
            for (int off = 1; off < 32; off <<= 1) {
                unsigned y = __shfl_down_sync(FULLM, suf, off);
                if (lane < 32 - off) suf += y;
            }
            unsigned S = cum + suf;
            unsigned bal = __ballot_sync(FULLM, S >= (unsigned)KC);
            if (bal) { tb = base + (31 - __clz(bal)); break; }
            cum += __shfl_sync(FULLM, suf, 0);
            if (base == 0) tb = 0;
        }
        if (lane == 0) { s_tb = tb; s_cnt = 0; }
        for (int i = lane; i < BINS; i += 32) g_hist[b*BINS + i] = 0;
    }
    __syncthreads();
    const int tb = s_tb;

    for (int n = tid; n < NA; n += 1024) {
        const float s = g_scores[b*NA + n];
        if (s > 0.0f && score_bin(s) >= tb) {
            int pos = atomicAdd(&s_cnt, 1);
            if (pos < CAP) {
                unsigned ob = ~__float_as_uint(s);
                sk[pos] = ((ull)ob << 32) | (unsigned)n;
            }
        }
    }
    __syncthreads();
    int cnt = s_cnt; if (cnt > CAP) cnt = CAP;
    for (int i = cnt + tid; i < CAP; i += 1024) sk[i] = ~0ull;
    __syncthreads();

    const int wp = tid >> 5, l = tid & 31;
    const int base = wp * 64;
    const int ia = base + l, ib = base + 32 + l;
    ull a = sk[ia], bb = sk[ib];

    #pragma unroll
    for (int size = 2; size <= 32; size <<= 1)
        #pragma unroll
        for (int stride = size >> 1; stride > 0; stride >>= 1) {
            a  = casx(a,  ia, stride, size);
            bb = casx(bb, ib, stride, size);
        }
    {
        bool up = ((ia & 64) == 0);
        if ((a > bb) == up) { ull t = a; a = bb; bb = t; }
        #pragma unroll
        for (int stride = 16; stride > 0; stride >>= 1) {
            a  = casx(a,  ia, stride, 64);
            bb = casx(bb, ib, stride, 64);
        }
    }
    sk[ia] = a; sk[ib] = bb;

    #pragma unroll
    for (int size = 128; size <= CAP; size <<= 1) {
        for (int stride = size >> 1; stride >= 64; stride >>= 1) {
            __syncthreads();
            const int pos = 2*tid - (tid & (stride - 1));
            ull A = sk[pos], B = sk[pos + stride];
            bool up = ((pos & size) == 0);
            if ((A > B) == up) { sk[pos] = B; sk[pos + stride] = A; }
        }
        __syncthreads();
        a = sk[ia]; bb = sk[ib];
        { bool up = ((ia & size) == 0);
          if ((a > bb) == up) { ull t = a; a = bb; bb = t; } }
        #pragma unroll
        for (int stride = 16; stride > 0; stride >>= 1) {
            a  = casx(a,  ia, stride, size);
            bb = casx(bb, ib, stride, size);
        }
        sk[ia] = a; sk[ib] = bb;
    }
    __syncthreads();

    const int vcnt = cnt < KC ? cnt : KC;
    const bool valid0 = tid < vcnt;
    float4 box = make_float4(0.f, 0.f, 0.f, 0.f);
    float area = 0.f, conf = 0.f; int cls = 0;
    if (valid0) {
        const ull key = sk[tid];
        const unsigned anchor = (unsigned)(key & 0xffffffffull);
        conf = __uint_as_float(~(unsigned)(key >> 32));
        const size_t pidx = ((size_t)b * NA + anchor) * PS;
        const float cx = pred[pidx + 0], cy = pred[pidx + 1];
        const float w  = pred[pidx + 2], h  = pred[pidx + 3];
        const float hw = __fmul_rn(w, 0.5f), hh = __fmul_rn(h, 0.5f);
        box.x = __fsub_rn(cx, hw); box.y = __fsub_rn(cy, hh);
        box.z = __fadd_rn(cx, hw); box.w = __fadd_rn(cy, hh);
        area  = __fmul_rn(__fsub_rn(box.z, box.x), __fsub_rn(box.w, box.y));
        cls   = g_cls[b*NA + anchor];
    }
    g_boxes[b*KC + tid]  = box;
    g_area[b*KC + tid]   = area;
    g_tscore[b*KC + tid] = conf;
    g_tcls[b*KC + tid]   = cls;
    const unsigned bal = __ballot_sync(FULLM, valid0);
    if ((tid & 31) == 0) g_validw[b*32 + (tid >> 5)] = bal;
}

// exact (vs JAX fp32) iou > 0.25
__device__ __forceinline__ bool iou_gt(float4 A, float aA, float4 B, float aB) {
    const float ltx = fmaxf(A.x, B.x), lty = fmaxf(A.y, B.y);
    const float rbx = fminf(A.z, B.z), rby = fminf(A.w, B.w);
    const float wx = fmaxf(__fsub_rn(rbx, ltx), 0.0f);
    const float wy = fmaxf(__fsub_rn(rby, lty), 0.0f);
    const float inter = __fmul_rn(wx, wy);
    const float denom = __fadd_rn(__fsub_rn(__fadd_rn(aA, aB), inter), 1e-9f);
    const float hi = __fmul_rn(IOU_T, denom);
    if (inter > __fmul_rn(hi, 1.00001f)) return true;
    if (inter < __fmul_rn(hi, 0.99999f)) return false;
    return __fdiv_rn(inter, denom) > IOU_T;
}

// ---------------- 3) suppression bits: lower triangle + diagonal word only ----------------
// row i, words w = 0..(i>>5): bit j set iff box j (j<i) overlaps box i (j suppresses i)
// grid (16, NB), 256 threads; rows interleaved across blocks for balance
__global__ void __launch_bounds__(256) k_mask() {
    __shared__ float4 sbx[KC];
    __shared__ float  sar[KC];
    const int b = blockIdx.y, tid = threadIdx.x;
    for (int i = tid; i < KC; i += 256) { sbx[i] = g_boxes[b*KC + i]; sar[i] = g_area[b*KC + i]; }
    __syncthreads();
    const int warp = tid >> 5, lane = tid & 31;
    for (int r = 0; r < 8; r++) {
        const int i = ((warp * 8 + r) << 4) + blockIdx.x;   // every-16th row per block
        const int wHi = i >> 5;
        const float4 A = sbx[i]; const float aA = sar[i];
        for (int w = 0; w <= wHi; w++) {
            const int j = w * 32 + lane;
            const bool c = (j < i) && iou_gt(A, aA, sbx[j], sar[j]);
            const unsigned bal = __ballot_sync(FULLM, c);
            if (lane == w) g_mask[((size_t)(b*KC + i)) * 32 + w] = bal;
        }
    }
}

// ---------------- 4) parallel greedy-NMS fixpoint + output (block = batch) ----------------
__global__ void __launch_bounds__(1024) k_scan_out(float* __restrict__ out,
                                                   const int* __restrict__ imgp,
                                                   int hasValid, int hasFeats) {
    extern __shared__ unsigned sm[];              // KC rows x SCAN_PITCH words (only 0..i>>5 live)
    __shared__ unsigned sU[32], sDK[32], sACT[32];
    __shared__ int wpre[32];
    __shared__ int s_done;
    const int b = blockIdx.x, tid = threadIdx.x;
    const int wid = tid >> 5, lane = tid & 31;

    // zero-fill this block's output slices (replaces the memset launch)
    {
        float* dets = out + (size_t)b * MAXDET * 6;
        for (int i = tid; i < MAXDET*6; i += 1024) dets[i] = 0.0f;
        for (int i = tid; i < MAXDET;   i += 1024) out[VALID_OFF + b*MAXDET + i] = 0.0f;
        if (b == 0) for (int i = tid; i < FEATS_LEN; i += 1024) out[FEATS_OFF + i] = 0.0f;
    }

    // stage triangle+diag words: row i needs words 0..(i>>5); warp per row stripe
    {
        const unsigned* gm = &g_mask[(size_t)b * KC * 32];
        for (int i = wid; i < KC; i += 32) {
            const int wHi = i >> 5;
            if (lane <= wHi) sm[i * SCAN_PITCH + lane] = gm[(size_t)i * 32 + lane];
        }
    }
    if (tid < 32) {
        unsigned v = g_validw[b*32 + tid];
        sU[tid] = v; sDK[tid] = 0u; sACT[tid] = v;
    }
    __syncthreads();

    // fixpoint: promote boxes with no ACTIVE suppressor below; kill boxes with a KEPT one
    const unsigned* row = &sm[tid * SCAN_PITCH];
    const unsigned belowSelf = (1u << lane) - 1u;
    for (int round = 0; round < 256; round++) {
        bool inU = (sU[wid] >> lane) & 1u;
        unsigned possible = 0;
        if (inU) {
            for (int w = 0; w < wid; w++) possible |= row[w] & sACT[w];
            possible |= row[wid] & sACT[wid] & belowSelf;
        }
        const unsigned promote = __ballot_sync(FULLM, inU && !possible);
        __syncthreads();
        if (lane == 0) { sDK[wid] |= promote; sU[wid] &= ~promote; }
        __syncthreads();

        inU = (sU[wid] >> lane) & 1u;
        unsigned definite = 0;
        if (inU) {
            for (int w = 0; w < wid; w++) definite |= row[w] & sDK[w];
            definite |= row[wid] & sDK[wid] & belowSelf;
        }
        const unsigned kill = __ballot_sync(FULLM, inU && (definite != 0));
        __syncthreads();
        if (lane == 0) sU[wid] &= ~kill;
        __syncthreads();

        if (tid < 32) {
            unsigned u = sU[tid];
            #pragma unroll
            for (int off = 16; off; off >>= 1) u |= __shfl_xor_sync(FULLM, u, off);
            if (tid == 0) s_done = (u == 0u);
            sACT[tid] = sU[tid] | sDK[tid];
        }
        __syncthreads();
        if (s_done) break;
    }

    // compact kept rows -> dets/valid/feats
    const unsigned kw = sDK[wid];
    if (tid < 32) {
        int v = __popc(sDK[tid]);
        int x = v;
        #pragma unroll
        for (int off = 1; off < 32; off <<= 1) {
            int y = __shfl_up_sync(FULLM, x, off);
            if (tid >= off) x += y;
        }
        wpre[tid] = x - v;
    }
    __syncthreads();
    const bool keep = (kw >> lane) & 1u;
    const int rank = wpre[wid] + __popc(kw & belowSelf);
    if (keep && rank < MAXDET) {
        const int idx = b*KC + tid;
        const float4 f = g_boxes[idx];
        const float sc = g_tscore[idx];
        const int   c  = g_tcls[idx];
        float* d = out + ((size_t)b * MAXDET + rank) * 6;
        d[0] = f.x; d[1] = f.y; d[2] = f.z; d[3] = f.w; d[4] = sc; d[5] = (float)c;
        if (hasValid) out[VALID_OFF + b*MAXDET + rank] = 1.0f;
        if (hasFeats && b == 0) {
            float scale = 1.0f / 640.0f;
            if (imgp) {
                int iv = imgp[0];
                if (iv > 0 && iv < 1000000) scale = 1.0f / (float)iv;
                else                        scale = 1.0f / __int_as_float(iv);
            }
            const size_t fo = (size_t)FEATS_OFF + (size_t)rank * 82;
            out[fo + 0] = __fmul_rn(__fmul_rn(__fadd_rn(f.x, f.z), 0.5f), scale);
            out[fo + 1] = __fmul_rn(__fmul_rn(__fadd_rn(f.y, f.w), 0.5f), scale);
            out[fo + 2 + c] = 1.0f;
        }
    }
}

extern "C" void kernel_launch(void* const* d_in, const int* in_sizes, int n_in,
                              void* d_out, int out_size) {
    const float* pred = (const float*)d_in[0];
    const int*   img  = (n_in > 1) ? (const int*)d_in[1] : nullptr;
    if (n_in > 1 && in_sizes[0] == 1) {
        img  = (const int*)d_in[0];
        pred = (const float*)d_in[1];
    }
    float* out = (float*)d_out;

    (void)cudaFuncSetAttribute(k_scan_out, cudaFuncAttributeMaxDynamicSharedMemorySize, SCAN_SMEM);

    k_score <<<dim3((NA + 127) / 128, NB), 256>>>(pred);
    k_prep  <<<NB, 1024>>>(pred);
    k_mask  <<<dim3(16, NB), 256>>>();

    const int hasValid = out_size >= VALID_OFF + NB*MAXDET;
    const int hasFeats = out_size >= FEATS_OFF + FEATS_LEN;
    k_scan_out<<<NB, 1024, SCAN_SMEM>>>(out, img, hasValid, hasFeats);
}

// round 9
// speedup vs baseline: 1.6466x; 1.0435x over previous
#include <cuda_runtime.h>
#include <cuda_bf16.h>
#include <stdint.h>

#define NB 16
#define NA 25200
#define NCLS 80
#define PS 85
#define KC 1024
#define CAP 2048
#define MAXDET 300
#define BINS 1024
#define CONF_T 0.4f
#define IOU_T 0.25f

#define DETS_OFF 0
#define VALID_OFF (NB*MAXDET*6)            // 28800
#define FEATS_OFF (VALID_OFF + NB*MAXDET)  // 33600
#define FEATS_LEN (MAXDET*82)              // 24600

#define SCAN_PITCH 33                      // odd => conflict-free LDS row stride
#define SCAN_SMEM (KC*SCAN_PITCH*4)        // 135168 B dynamic shared

typedef unsigned long long ull;
#define FULLM 0xffffffffu

// ---------------- device scratch (no allocs allowed) ----------------
__device__ float               g_scores[NB*NA];
__device__ int                 g_cls[NB*NA];
__device__ unsigned int        g_hist[NB*BINS];   // zero at load; re-zeroed each call in k_prep
__device__ float4              g_boxes[NB*KC];
__device__ float               g_area[NB*KC];
__device__ float               g_tscore[NB*KC];
__device__ int                 g_tcls[NB*KC];
__device__ unsigned int        g_validw[NB*32];
__device__ unsigned int        g_mask[NB*KC*32];  // lower-triangle+diag words only are live

__device__ __forceinline__ int score_bin(float s) {
    float bf = __fmul_rn(__fsub_rn(s, CONF_T), (float)BINS / 0.6f);
    int b = (int)bf;
    return b > (BINS-1) ? (BINS-1) : (b < 0 ? 0 : b);
}

// ---------------- 1) score + histogram ----------------
__global__ void __launch_bounds__(256) k_score(const float* __restrict__ pred) {
    __shared__ float sb[128*PS];
    const int b   = blockIdx.y;
    const int a0  = blockIdx.x * 128;
    const int tid = threadIdx.x;
    const int na  = (NA - a0) < 128 ? (NA - a0) : 128;

    const float* base = pred + ((size_t)b * NA + a0) * PS;
    const int total4 = (na * PS) >> 2;
    const float4* g4 = (const float4*)base;
    float4* s4 = (float4*)sb;
    for (int i = tid; i < total4; i += 256) s4[i] = __ldcs(g4 + i);   // streaming: read-once data
    __syncthreads();

    if (tid < na) {
        const float* p = sb + tid * PS;
        const float obj = p[4];
        float best = -1e30f; int arg = 0;
        #pragma unroll 8
        for (int c = 0; c < NCLS; c++) {
            float v = __fmul_rn(p[5 + c], obj);
            if (v > best) { best = v; arg = c; }   // strict > = lowest-index argmax tie rule
        }
        const bool cand = (obj > CONF_T) && (best > CONF_T);
        const int n = a0 + tid;
        g_scores[b*NA + n] = cand ? best : -1.0f;
        g_cls[b*NA + n]    = arg;
        if (cand) atomicAdd(&g_hist[b*BINS + score_bin(best)], 1u);
    }
}

// hybrid bitonic compare-exchange: shuffle pass for stride<=16
__device__ __forceinline__ ull casx(ull x, int idx, int stride, int size) {
    ull p = __shfl_xor_sync(FULLM, x, stride);
    bool lower = ((idx & stride) == 0);
    bool up    = ((idx & size)   == 0);
    return (lower == up) ? (x < p ? x : p) : (x > p ? x : p);
}

// ---------------- 2) fused: threshold + gather + sort + box emit (block = batch) ----------
__global__ void __launch_bounds__(1024) k_prep(const float* __restrict__ pred) {
    __shared__ ull sk[CAP];
    __shared__ int s_tb, s_cnt;
    const int b = blockIdx.x, tid = threadIdx.x;

    if (tid < 32) {
        const int lane = tid;
        unsigned cum = 0; int tb = 0;
        for (int base = BINS - 32; base >= 0; base -= 32) {
            unsigned v = g_hist[b*BINS + base + lane];
            unsigned suf = v;
            #pragma unroll
            for (int off = 1; off < 32; off <<= 1) {
                unsigned y = __shfl_down_sync(FULLM, suf, off);
                if (lane < 32 - off) suf += y;
            }
            unsigned S = cum + suf;
            unsigned bal = __ballot_sync(FULLM, S >= (unsigned)KC);
            if (bal) { tb = base + (31 - __clz(bal)); break; }
            cum += __shfl_sync(FULLM, suf, 0);
            if (base == 0) tb = 0;
        }
        if (lane == 0) { s_tb = tb; s_cnt = 0; }
        for (int i = lane; i < BINS; i += 32) g_hist[b*BINS + i] = 0;
    }
    __syncthreads();
    const int tb = s_tb;

    for (int n = tid; n < NA; n += 1024) {
        const float s = g_scores[b*NA + n];
        if (s > 0.0f && score_bin(s) >= tb) {
            int pos = atomicAdd(&s_cnt, 1);
            if (pos < CAP) {
                unsigned ob = ~__float_as_uint(s);
                sk[pos] = ((ull)ob << 32) | (unsigned)n;
            }
        }
    }
    __syncthreads();
    int cnt = s_cnt; if (cnt > CAP) cnt = CAP;
    for (int i = cnt + tid; i < CAP; i += 1024) sk[i] = ~0ull;
    __syncthreads();

    const int wp = tid >> 5, l = tid & 31;
    const int base = wp * 64;
    const int ia = base + l, ib = base + 32 + l;
    ull a = sk[ia], bb = sk[ib];

    #pragma unroll
    for (int size = 2; size <= 32; size <<= 1)
        #pragma unroll
        for (int stride = size >> 1; stride > 0; stride >>= 1) {
            a  = casx(a,  ia, stride, size);
            bb = casx(bb, ib, stride, size);
        }
    {
        bool up = ((ia & 64) == 0);
        if ((a > bb) == up) { ull t = a; a = bb; bb = t; }
        #pragma unroll
        for (int stride = 16; stride > 0; stride >>= 1) {
            a  = casx(a,  ia, stride, 64);
            bb = casx(bb, ib, stride, 64);
        }
    }
    sk[ia] = a; sk[ib] = bb;

    #pragma unroll
    for (int size = 128; size <= CAP; size <<= 1) {
        for (int stride = size >> 1; stride >= 64; stride >>= 1) {
            __syncthreads();
            const int pos = 2*tid - (tid & (stride - 1));
            ull A = sk[pos], B = sk[pos + stride];
            bool up = ((pos & size) == 0);
            if ((A > B) == up) { sk[pos] = B; sk[pos + stride] = A; }
        }
        __syncthreads();
        a = sk[ia]; bb = sk[ib];
        { bool up = ((ia & size) == 0);
          if ((a > bb) == up) { ull t = a; a = bb; bb = t; } }
        #pragma unroll
        for (int stride = 16; stride > 0; stride >>= 1) {
            a  = casx(a,  ia, stride, size);
            bb = casx(bb, ib, stride, size);
        }
        sk[ia] = a; sk[ib] = bb;
    }
    __syncthreads();

    const int vcnt = cnt < KC ? cnt : KC;
    const bool valid0 = tid < vcnt;
    float4 box = make_float4(0.f, 0.f, 0.f, 0.f);
    float area = 0.f, conf = 0.f; int cls = 0;
    if (valid0) {
        const ull key = sk[tid];
        const unsigned anchor = (unsigned)(key & 0xffffffffull);
        conf = __uint_as_float(~(unsigned)(key >> 32));
        const size_t pidx = ((size_t)b * NA + anchor) * PS;
        const float cx = pred[pidx + 0], cy = pred[pidx + 1];
        const float w  = pred[pidx + 2], h  = pred[pidx + 3];
        const float hw = __fmul_rn(w, 0.5f), hh = __fmul_rn(h, 0.5f);
        box.x = __fsub_rn(cx, hw); box.y = __fsub_rn(cy, hh);
        box.z = __fadd_rn(cx, hw); box.w = __fadd_rn(cy, hh);
        area  = __fmul_rn(__fsub_rn(box.z, box.x), __fsub_rn(box.w, box.y));
        cls   = g_cls[b*NA + anchor];
    }
    g_boxes[b*KC + tid]  = box;
    g_area[b*KC + tid]   = area;
    g_tscore[b*KC + tid] = conf;
    g_tcls[b*KC + tid]   = cls;
    const unsigned bal = __ballot_sync(FULLM, valid0);
    if ((tid & 31) == 0) g_validw[b*32 + (tid >> 5)] = bal;
}

// exact (vs JAX fp32) iou > 0.25
__device__ __forceinline__ bool iou_gt(float4 A, float aA, float4 B, float aB) {
    const float ltx = fmaxf(A.x, B.x), lty = fmaxf(A.y, B.y);
    const float rbx = fminf(A.z, B.z), rby = fminf(A.w, B.w);
    const float wx = fmaxf(__fsub_rn(rbx, ltx), 0.0f);
    const float wy = fmaxf(__fsub_rn(rby, lty), 0.0f);
    const float inter = __fmul_rn(wx, wy);
    const float denom = __fadd_rn(__fsub_rn(__fadd_rn(aA, aB), inter), 1e-9f);
    const float hi = __fmul_rn(IOU_T, denom);
    if (inter > __fmul_rn(hi, 1.00001f)) return true;
    if (inter < __fmul_rn(hi, 0.99999f)) return false;
    return __fdiv_rn(inter, denom) > IOU_T;
}

// ---------------- 3) suppression bits: lower triangle + diagonal word only ----------------
__global__ void __launch_bounds__(256) k_mask() {
    __shared__ float4 sbx[KC];
    __shared__ float  sar[KC];
    const int b = blockIdx.y, tid = threadIdx.x;
    for (int i = tid; i < KC; i += 256) { sbx[i] = g_boxes[b*KC + i]; sar[i] = g_area[b*KC + i]; }
    __syncthreads();
    const int warp = tid >> 5, lane = tid & 31;
    for (int r = 0; r < 8; r++) {
        const int i = ((warp * 8 + r) << 4) + blockIdx.x;   // every-16th row per block
        const int wHi = i >> 5;
        const float4 A = sbx[i]; const float aA = sar[i];
        for (int w = 0; w <= wHi; w++) {
            const int j = w * 32 + lane;
            const bool c = (j < i) && iou_gt(A, aA, sbx[j], sar[j]);
            const unsigned bal = __ballot_sync(FULLM, c);
            if (lane == w) g_mask[((size_t)(b*KC + i)) * 32 + w] = bal;
        }
    }
}

// ---------------- 4) parallel greedy-NMS fixpoint (live-word pruned) + output ----------------
__global__ void __launch_bounds__(1024) k_scan_out(float* __restrict__ out,
                                                   const int* __restrict__ imgp,
                                                   int hasValid, int hasFeats) {
    extern __shared__ unsigned sm[];              // KC rows x SCAN_PITCH words (only 0..i>>5 live)
    __shared__ unsigned sU[32], sDK[32], sACT[32];
    __shared__ int wpre[32];
    __shared__ int s_done;
    const int b = blockIdx.x, tid = threadIdx.x;
    const int wid = tid >> 5, lane = tid & 31;

    // zero-fill this block's output slices (replaces the memset launch)
    {
        float* dets = out + (size_t)b * MAXDET * 6;
        for (int i = tid; i < MAXDET*6; i += 1024) dets[i] = 0.0f;
        for (int i = tid; i < MAXDET;   i += 1024) out[VALID_OFF + b*MAXDET + i] = 0.0f;
        if (b == 0) for (int i = tid; i < FEATS_LEN; i += 1024) out[FEATS_OFF + i] = 0.0f;
    }

    // stage triangle+diag words: row i needs words 0..(i>>5); warp per row stripe
    {
        const unsigned* gm = &g_mask[(size_t)b * KC * 32];
        for (int i = wid; i < KC; i += 32) {
            const int wHi = i >> 5;
            if (lane <= wHi) sm[i * SCAN_PITCH + lane] = gm[(size_t)i * 32 + lane];
        }
    }
    if (tid < 32) {
        unsigned v = g_validw[b*32 + tid];
        sU[tid] = v; sDK[tid] = 0u; sACT[tid] = v;
    }
    __syncthreads();

    // live words: bits w where row[w] has any suppressor bit (sparse for random boxes)
    const unsigned* row = &sm[tid * SCAN_PITCH];
    unsigned lw = 0;
    for (int w = 0; w <= wid; w++)
        if (row[w]) lw |= (1u << w);      // row[wid] already contains only j<i bits

    // fixpoint: merged promote/kill pass; only live words are scanned
    for (int round = 0; round < 256; round++) {
        const bool inU = (sU[wid] >> lane) & 1u;
        bool poss = false; unsigned def = 0;
        if (inU) {
            unsigned m = lw;
            while (m) {
                const int w = __ffs(m) - 1; m &= m - 1;
                const unsigned x = row[w];
                const unsigned a = x & sACT[w];
                if (!a) { lw &= ~(1u << w); continue; }   // permanently dead word
                poss = true;
                def |= x & sDK[w];
            }
        }
        const unsigned promote = __ballot_sync(FULLM, inU && !poss);
        const unsigned kill    = __ballot_sync(FULLM, inU && (def != 0));
        __syncthreads();                                  // all reads of old state done
        if (lane == 0) { sDK[wid] |= promote; sU[wid] &= ~(promote | kill); }
        __syncthreads();
        if (tid < 32) {
            sACT[tid] = sU[tid] | sDK[tid];
            unsigned u = sU[tid];
            #pragma unroll
            for (int off = 16; off; off >>= 1) u |= __shfl_xor_sync(FULLM, u, off);
            if (tid == 0) s_done = (u == 0u);
        }
        __syncthreads();
        if (s_done) break;
    }

    // compact kept rows -> dets/valid/feats
    const unsigned belowSelf = (1u << lane) - 1u;
    const unsigned kw = sDK[wid];
    if (tid < 32) {
        int v = __popc(sDK[tid]);
        int x = v;
        #pragma unroll
        for (int off = 1; off < 32; off <<= 1) {
            int y = __shfl_up_sync(FULLM, x, off);
            if (tid >= off) x += y;
        }
        wpre[tid] = x - v;
    }
    __syncthreads();
    const bool keep = (kw >> lane) & 1u;
    const int rank = wpre[wid] + __popc(kw & belowSelf);
    if (keep && rank < MAXDET) {
        const int idx = b*KC + tid;
        const float4 f = g_boxes[idx];
        const float sc = g_tscore[idx];
        const int   c  = g_tcls[idx];
        float* d = out + ((size_t)b * MAXDET + rank) * 6;
        d[0] = f.x; d[1] = f.y; d[2] = f.z; d[3] = f.w; d[4] = sc; d[5] = (float)c;
        if (hasValid) out[VALID_OFF + b*MAXDET + rank] = 1.0f;
        if (hasFeats && b == 0) {
            float scale = 1.0f / 640.0f;
            if (imgp) {
                int iv = imgp[0];
                if (iv > 0 && iv < 1000000) scale = 1.0f / (float)iv;
                else                        scale = 1.0f / __int_as_float(iv);
            }
            const size_t fo = (size_t)FEATS_OFF + (size_t)rank * 82;
            out[fo + 0] = __fmul_rn(__fmul_rn(__fadd_rn(f.x, f.z), 0.5f), scale);
            out[fo + 1] = __fmul_rn(__fmul_rn(__fadd_rn(f.y, f.w), 0.5f), scale);
            out[fo + 2 + c] = 1.0f;
        }
    }
}

extern "C" void kernel_launch(void* const* d_in, const int* in_sizes, int n_in,
                              void* d_out, int out_size) {
    const float* pred = (const float*)d_in[0];
    const int*   img  = (n_in > 1) ? (const int*)d_in[1] : nullptr;
    if (n_in > 1 && in_sizes[0] == 1) {
        img  = (const int*)d_in[0];
        pred = (const float*)d_in[1];
    }
    float* out = (float*)d_out;

    (void)cudaFuncSetAttribute(k_scan_out, cudaFuncAttributeMaxDynamicSharedMemorySize, SCAN_SMEM);

    k_score <<<dim3((NA + 127) / 128, NB), 256>>>(pred);
    k_prep  <<<NB, 1024>>>(pred);
    k_mask  <<<dim3(16, NB), 256>>>();

    const int hasValid = out_size >= VALID_OFF + NB*MAXDET;
    const int hasFeats = out_size >= FEATS_OFF + FEATS_LEN;
    k_scan_out<<<NB, 1024, SCAN_SMEM>>>(out, img, hasValid, hasFeats);
}